// round 13
// baseline (speedup 1.0000x reference)
#include <cuda_runtime.h>
#include <cuda_fp16.h>
#include <cstdint>

// BlockLinear, weight-resident, 16 warps: each CTA owns one (nb, m-half);
// converts W[nb] (256x256) to fp16 SMEM once, then streams 16 M-slabs of 128.
// CTA tile 128x256, 16 warps of 32x64 (4M x 4N), K chunks of 64, dbl-buffered A.

#define THREADS 512
#define ARB 144                    // A smem row bytes: 9 units -> conflict-free
#define BRB 528                    // B smem row bytes: 33 units -> conflict-free
#define A_STG (128 * ARB)          // 18432 B per A stage
#define SM_A 0
#define SM_B (2 * A_STG)           // 36864
#define SM_BIAS (SM_B + 256 * BRB) // 172032
#define SMEM_TOTAL (SM_BIAS + 1024)

__device__ __forceinline__ uint32_t pk2(float a, float b) {
    __half2 h = __floats2half2_rn(a, b);
    return *reinterpret_cast<uint32_t*>(&h);
}
__device__ __forceinline__ void ldm4(uint32_t* r, uint32_t addr) {
    asm volatile("ldmatrix.sync.aligned.m8n8.x4.shared.b16 {%0,%1,%2,%3}, [%4];"
                 : "=r"(r[0]), "=r"(r[1]), "=r"(r[2]), "=r"(r[3]) : "r"(addr));
}
__device__ __forceinline__ void mma16816(float* c, const uint32_t* a, const uint32_t* b) {
    asm volatile(
        "mma.sync.aligned.m16n8k16.row.col.f32.f16.f16.f32 "
        "{%0,%1,%2,%3},{%4,%5,%6,%7},{%8,%9},{%0,%1,%2,%3};"
        : "+f"(c[0]), "+f"(c[1]), "+f"(c[2]), "+f"(c[3])
        : "r"(a[0]), "r"(a[1]), "r"(a[2]), "r"(a[3]), "r"(b[0]), "r"(b[1]));
}

__global__ __launch_bounds__(THREADS, 1)
void block_linear_wres(const float* __restrict__ X, const float* __restrict__ W,
                       const float* __restrict__ Bias, float* __restrict__ Y)
{
    extern __shared__ unsigned char sm[];
    const uint32_t smu = (uint32_t)__cvta_generic_to_shared(sm);

    const int nb = blockIdx.x;          // diag block 0..63
    const int by = blockIdx.y;          // m-half 0..1 (16 slabs each)

    const int tid  = threadIdx.x;
    const int warp = tid >> 5;
    const int lane = tid & 31;
    const int wm   = warp & 3;          // 4 warp-groups along M (32 rows)
    const int wn   = warp >> 2;         // 4 along N (64 cols)
    const int g    = lane >> 2;
    const int tg   = lane & 3;

    // ---- bias to smem ----
    if (tid < 256) ((float*)(sm + SM_BIAS))[tid] = Bias[nb * 256 + tid];

    // ---- one-time: convert W[nb] (256 rows x 256 k fp32) -> fp16 smem ----
    {
        const int brow = tid >> 1;          // 0..255
        const int bh   = tid & 1;           // half-row: 128 floats
        const float4* wr = (const float4*)(W + (size_t)nb * 65536
                                             + (size_t)brow * 256 + bh * 128);
        unsigned char* bdst = sm + SM_B + brow * BRB + bh * 256;
        #pragma unroll
        for (int j = 0; j < 16; ++j) {
            float4 v0 = wr[2 * j], v1 = wr[2 * j + 1];
            uint4 o = {pk2(v0.x, v0.y), pk2(v0.z, v0.w), pk2(v1.x, v1.y), pk2(v1.z, v1.w)};
            *(uint4*)(bdst + j * 16) = o;
        }
    }

    // ---- A fill mapping: thread -> row r, 16-float segment seg ----
    const int r   = tid >> 2;           // 0..127
    const int seg = tid & 3;            // k-segment of 16 floats
    const float* xbase = X + (size_t)nb * 256 + seg * 16;
    unsigned char* aS = sm + SM_A;
    const uint32_t asts = (uint32_t)(r * ARB + seg * 32);

    // ---- ldmatrix lane addressing ----
    const int la = lane & 15, ha = lane >> 4;
    const uint32_t aAddr = smu + SM_A + (wm * 32 + la) * ARB + ha * 16;
    const int lb = (lane & 7) + ((lane >> 4) << 3);
    const int cb = (lane >> 3) & 1;
    const uint32_t bAddr = smu + SM_B + (wn * 64 + lb) * BRB + cb * 16;

    float acc[2][8][4];
    #pragma unroll
    for (int mt = 0; mt < 2; ++mt)
        #pragma unroll
        for (int nt = 0; nt < 8; ++nt)
            #pragma unroll
            for (int i = 0; i < 4; ++i) acc[mt][nt][i] = 0.0f;

    // ---- prologue: chunk 0 -> stage 0 ----
    {
        const float* xr = xbase + (size_t)(by * 2048 + r) * 16384;
        #pragma unroll
        for (int j = 0; j < 2; ++j) {
            float4 v0 = *(const float4*)(xr + j * 8);
            float4 v1 = *(const float4*)(xr + j * 8 + 4);
            uint4 o = {pk2(v0.x, v0.y), pk2(v0.z, v0.w), pk2(v1.x, v1.y), pk2(v1.z, v1.w)};
            *(uint4*)(aS + asts + j * 16) = o;
        }
    }
    __syncthreads();

    // ---- main loop: 64 chunks = 16 slabs x 4 K-chunks ----
    #pragma unroll 1
    for (int c = 0; c < 64; ++c) {
        const int p = c & 1;

        // prefetch next chunk's X into regs (hidden under compute)
        float4 pf[4];
        if (c < 63) {
            const int cn  = c + 1;
            const int m0n = (by * 16 + (cn >> 2)) * 128;
            const int kbn = (cn & 3) * 64;
            const float* xr = xbase + (size_t)(m0n + r) * 16384 + kbn;
            #pragma unroll
            for (int j = 0; j < 4; ++j)
                pf[j] = *(const float4*)(xr + j * 4);
        }

        // compute chunk c from stage p: 4 k16-steps, warp tile 32x64
        const uint32_t aB = aAddr + p * A_STG;
        const uint32_t bB = bAddr + (c & 3) * 128;
        #pragma unroll
        for (int ks = 0; ks < 4; ++ks) {
            uint32_t aF[2][4], bF[8][2];
            #pragma unroll
            for (int mt = 0; mt < 2; ++mt)
                ldm4(aF[mt], aB + mt * 16 * ARB + ks * 32);
            #pragma unroll
            for (int q = 0; q < 4; ++q) {
                uint32_t t[4];
                ldm4(t, bB + q * 16 * BRB + ks * 32);
                bF[2 * q][0]     = t[0]; bF[2 * q][1]     = t[1];
                bF[2 * q + 1][0] = t[2]; bF[2 * q + 1][1] = t[3];
            }
            #pragma unroll
            for (int nt = 0; nt < 8; ++nt)
                #pragma unroll
                for (int mt = 0; mt < 2; ++mt)
                    mma16816(acc[mt][nt], aF[mt], bF[nt]);
        }

        // slab finished? epilogue + reset accs
        if ((c & 3) == 3) {
            const int m0 = (by * 16 + (c >> 2)) * 128;
            const float* bs = (const float*)(sm + SM_BIAS);
            #pragma unroll
            for (int mt = 0; mt < 2; ++mt) {
                const int row0 = m0 + wm * 32 + mt * 16 + g;
                #pragma unroll
                for (int nt = 0; nt < 8; ++nt) {
                    const int lcol = wn * 64 + nt * 8 + tg * 2;
                    const int gcol = nb * 256 + lcol;
                    const float b0 = bs[lcol], b1 = bs[lcol + 1];
                    float2 v0 = make_float2(acc[mt][nt][0] + b0, acc[mt][nt][1] + b1);
                    float2 v1 = make_float2(acc[mt][nt][2] + b0, acc[mt][nt][3] + b1);
                    *(float2*)(Y + (size_t)row0       * 16384 + gcol) = v0;
                    *(float2*)(Y + (size_t)(row0 + 8) * 16384 + gcol) = v1;
                    acc[mt][nt][0] = 0.0f; acc[mt][nt][1] = 0.0f;
                    acc[mt][nt][2] = 0.0f; acc[mt][nt][3] = 0.0f;
                }
            }
        }

        // store prefetched chunk into other stage
        if (c < 63) {
            unsigned char* dst = aS + (p ^ 1) * A_STG + asts;
            #pragma unroll
            for (int j = 0; j < 2; ++j) {
                uint4 o = {pk2(pf[2*j].x, pf[2*j].y),     pk2(pf[2*j].z, pf[2*j].w),
                           pk2(pf[2*j+1].x, pf[2*j+1].y), pk2(pf[2*j+1].z, pf[2*j+1].w)};
                *(uint4*)(dst + j * 16) = o;
            }
        }
        __syncthreads();
    }
}

extern "C" void kernel_launch(void* const* d_in, const int* in_sizes, int n_in,
                              void* d_out, int out_size) {
    const float* x    = (const float*)d_in[0];
    const float* w    = (const float*)d_in[1];
    const float* bias = (const float*)d_in[2];
    float* y          = (float*)d_out;

    cudaFuncSetAttribute(block_linear_wres,
                         cudaFuncAttributeMaxDynamicSharedMemorySize, SMEM_TOTAL);
    dim3 grid(64, 2);   // (diag block, m-half) -> 128 CTAs, one wave
    block_linear_wres<<<grid, THREADS, SMEM_TOTAL>>>(x, w, bias, y);
}

// round 14
// speedup vs baseline: 1.1227x; 1.1227x over previous
#include <cuda_runtime.h>
#include <cuda_fp16.h>
#include <cstdint>

// BlockLinear, weight-resident: CTA owns (nb, m-half). W[nb] -> fp16 smem once,
// stream 16 M-slabs of 128 rows. CTA tile 128x256, 8 warps of 64x64,
// K chunk = 128 (one barrier per chunk, 32 total), dbl-buffered A, 2-round fill.

#define THREADS 256
#define ARB 272                    // A smem row bytes: 17 units -> conflict-free
#define BRB 528                    // B smem row bytes: 33 units -> conflict-free
#define A_STG (128 * ARB)          // 34816 B per A stage
#define SM_A 0
#define SM_B (2 * A_STG)           // 69632
#define SM_BIAS (SM_B + 256 * BRB) // 204800
#define SMEM_TOTAL (SM_BIAS + 1024)

__device__ __forceinline__ uint32_t pk2(float a, float b) {
    __half2 h = __floats2half2_rn(a, b);
    return *reinterpret_cast<uint32_t*>(&h);
}
__device__ __forceinline__ void ldm4(uint32_t* r, uint32_t addr) {
    asm volatile("ldmatrix.sync.aligned.m8n8.x4.shared.b16 {%0,%1,%2,%3}, [%4];"
                 : "=r"(r[0]), "=r"(r[1]), "=r"(r[2]), "=r"(r[3]) : "r"(addr));
}
__device__ __forceinline__ void mma16816(float* c, const uint32_t* a, const uint32_t* b) {
    asm volatile(
        "mma.sync.aligned.m16n8k16.row.col.f32.f16.f16.f32 "
        "{%0,%1,%2,%3},{%4,%5,%6,%7},{%8,%9},{%0,%1,%2,%3};"
        : "+f"(c[0]), "+f"(c[1]), "+f"(c[2]), "+f"(c[3])
        : "r"(a[0]), "r"(a[1]), "r"(a[2]), "r"(a[3]), "r"(b[0]), "r"(b[1]));
}

__global__ __launch_bounds__(THREADS, 1)
void block_linear_wres(const float* __restrict__ X, const float* __restrict__ W,
                       const float* __restrict__ Bias, float* __restrict__ Y)
{
    extern __shared__ unsigned char sm[];
    const uint32_t smu = (uint32_t)__cvta_generic_to_shared(sm);

    const int nb = blockIdx.x;          // diag block 0..63
    const int by = blockIdx.y;          // m-half 0..1 (16 slabs each)

    const int tid  = threadIdx.x;
    const int warp = tid >> 5;
    const int lane = tid & 31;
    const int wm   = warp & 1;          // 2 warps along M (64 rows)
    const int wn   = warp >> 1;         // 4 warps along N (64 cols)
    const int g    = lane >> 2;
    const int tg   = lane & 3;

    // ---- bias to smem ----
    ((float*)(sm + SM_BIAS))[tid] = Bias[nb * 256 + tid];

    // ---- one-time: convert W[nb] (256x256 fp32) -> fp16 smem ----
    {
        const float4* wr = (const float4*)(W + (size_t)nb * 65536 + (size_t)tid * 256);
        unsigned char* brow = sm + SM_B + tid * BRB;
        #pragma unroll 8
        for (int j = 0; j < 32; ++j) {
            float4 v0 = wr[2 * j], v1 = wr[2 * j + 1];
            uint4 o = {pk2(v0.x, v0.y), pk2(v0.z, v0.w), pk2(v1.x, v1.y), pk2(v1.z, v1.w)};
            *(uint4*)(brow + j * 16) = o;
        }
    }

    // ---- A fill mapping: row r = tid&127, seg = tid>>7 (64-col half of a 128-chunk)
    const int r   = tid & 127;
    const int seg = tid >> 7;
    const float* xbase = X + (size_t)nb * 256 + seg * 64;   // +round*32 + chunk k
    unsigned char* aS = sm + SM_A;
    const uint32_t asts = (uint32_t)(r * ARB + seg * 128);  // +round*64

    // ---- ldmatrix lane addressing ----
    const int la = lane & 15, ha = lane >> 4;
    const uint32_t aAddr = smu + SM_A + (wm * 64 + la) * ARB + ha * 16;
    const int lb = (lane & 7) + ((lane >> 4) << 3);
    const int cb = (lane >> 3) & 1;
    const uint32_t bAddr = smu + SM_B + (wn * 64 + lb) * BRB + cb * 16;

    float acc[4][8][4];
    #pragma unroll
    for (int mt = 0; mt < 4; ++mt)
        #pragma unroll
        for (int nt = 0; nt < 8; ++nt)
            #pragma unroll
            for (int i = 0; i < 4; ++i) acc[mt][nt][i] = 0.0f;

    // ---- prologue: chunk 0 (slab 0, k 0..127) -> stage 0, both rounds ----
    {
        const float* xr = xbase + (size_t)(by * 2048 + r) * 16384;
        #pragma unroll
        for (int rd = 0; rd < 2; ++rd) {
            #pragma unroll
            for (int j = 0; j < 4; ++j) {
                float4 v0 = *(const float4*)(xr + rd * 32 + j * 8);
                float4 v1 = *(const float4*)(xr + rd * 32 + j * 8 + 4);
                uint4 o = {pk2(v0.x, v0.y), pk2(v0.z, v0.w), pk2(v1.x, v1.y), pk2(v1.z, v1.w)};
                *(uint4*)(aS + asts + rd * 64 + j * 16) = o;
            }
        }
    }
    __syncthreads();

    // ---- main loop: 32 chunks = 16 slabs x 2 K-chunks of 128 ----
    #pragma unroll 1
    for (int c = 0; c < 32; ++c) {
        const int p = c & 1;
        const uint32_t aB = aAddr + p * A_STG;
        const uint32_t bB = bAddr + p * 256;    // k-half of slab: (c&1)*128 cols * 2B

        // next-chunk gmem base for this thread
        const float* xn = nullptr;
        if (c < 31) {
            const int cn = c + 1;
            xn = xbase + (size_t)((by * 16 + (cn >> 1)) * 128 + r) * 16384
                       + (cn & 1) * 128;
        }

        float4 pf[8];
        // round-0 LDG for chunk c+1 (lands during ks0-3)
        if (c < 31) {
            #pragma unroll
            for (int j = 0; j < 8; ++j) pf[j] = *(const float4*)(xn + j * 4);
        }

        // ---- compute ks 0..3 ----
        #pragma unroll
        for (int ks = 0; ks < 4; ++ks) {
            uint32_t aF[4][4], bF[8][2];
            #pragma unroll
            for (int mt = 0; mt < 4; ++mt)
                ldm4(aF[mt], aB + mt * 16 * ARB + ks * 32);
            #pragma unroll
            for (int q = 0; q < 4; ++q) {
                uint32_t t[4];
                ldm4(t, bB + q * 16 * BRB + ks * 32);
                bF[2 * q][0]     = t[0]; bF[2 * q][1]     = t[1];
                bF[2 * q + 1][0] = t[2]; bF[2 * q + 1][1] = t[3];
            }
            #pragma unroll
            for (int nt = 0; nt < 8; ++nt)
                #pragma unroll
                for (int mt = 0; mt < 4; ++mt)
                    mma16816(acc[mt][nt], aF[mt], bF[nt]);
        }

        // STS round-0 into other stage; LDG round-1
        if (c < 31) {
            unsigned char* dst = aS + (p ^ 1) * A_STG + asts;
            #pragma unroll
            for (int j = 0; j < 4; ++j) {
                uint4 o = {pk2(pf[2*j].x, pf[2*j].y),     pk2(pf[2*j].z, pf[2*j].w),
                           pk2(pf[2*j+1].x, pf[2*j+1].y), pk2(pf[2*j+1].z, pf[2*j+1].w)};
                *(uint4*)(dst + j * 16) = o;
            }
            #pragma unroll
            for (int j = 0; j < 8; ++j) pf[j] = *(const float4*)(xn + 32 + j * 4);
        }

        // ---- compute ks 4..7 ----
        #pragma unroll
        for (int ks = 4; ks < 8; ++ks) {
            uint32_t aF[4][4], bF[8][2];
            #pragma unroll
            for (int mt = 0; mt < 4; ++mt)
                ldm4(aF[mt], aB + mt * 16 * ARB + ks * 32);
            #pragma unroll
            for (int q = 0; q < 4; ++q) {
                uint32_t t[4];
                ldm4(t, bB + q * 16 * BRB + ks * 32);
                bF[2 * q][0]     = t[0]; bF[2 * q][1]     = t[1];
                bF[2 * q + 1][0] = t[2]; bF[2 * q + 1][1] = t[3];
            }
            #pragma unroll
            for (int nt = 0; nt < 8; ++nt)
                #pragma unroll
                for (int mt = 0; mt < 4; ++mt)
                    mma16816(acc[mt][nt], aF[mt], bF[nt]);
        }

        // STS round-1 into other stage
        if (c < 31) {
            unsigned char* dst = aS + (p ^ 1) * A_STG + asts + 64;
            #pragma unroll
            for (int j = 0; j < 4; ++j) {
                uint4 o = {pk2(pf[2*j].x, pf[2*j].y),     pk2(pf[2*j].z, pf[2*j].w),
                           pk2(pf[2*j+1].x, pf[2*j+1].y), pk2(pf[2*j+1].z, pf[2*j+1].w)};
                *(uint4*)(dst + j * 16) = o;
            }
        }

        // slab finished? epilogue + reset accs
        if (p == 1) {
            const int m0 = (by * 16 + (c >> 1)) * 128;
            const float* bs = (const float*)(sm + SM_BIAS);
            #pragma unroll
            for (int mt = 0; mt < 4; ++mt) {
                const int row0 = m0 + wm * 64 + mt * 16 + g;
                #pragma unroll
                for (int nt = 0; nt < 8; ++nt) {
                    const int lcol = wn * 64 + nt * 8 + tg * 2;
                    const int gcol = nb * 256 + lcol;
                    const float b0 = bs[lcol], b1 = bs[lcol + 1];
                    float2 v0 = make_float2(acc[mt][nt][0] + b0, acc[mt][nt][1] + b1);
                    float2 v1 = make_float2(acc[mt][nt][2] + b0, acc[mt][nt][3] + b1);
                    *(float2*)(Y + (size_t)row0       * 16384 + gcol) = v0;
                    *(float2*)(Y + (size_t)(row0 + 8) * 16384 + gcol) = v1;
                    acc[mt][nt][0] = 0.0f; acc[mt][nt][1] = 0.0f;
                    acc[mt][nt][2] = 0.0f; acc[mt][nt][3] = 0.0f;
                }
            }
        }
        __syncthreads();
    }
}

extern "C" void kernel_launch(void* const* d_in, const int* in_sizes, int n_in,
                              void* d_out, int out_size) {
    const float* x    = (const float*)d_in[0];
    const float* w    = (const float*)d_in[1];
    const float* bias = (const float*)d_in[2];
    float* y          = (float*)d_out;

    cudaFuncSetAttribute(block_linear_wres,
                         cudaFuncAttributeMaxDynamicSharedMemorySize, SMEM_TOTAL);
    dim3 grid(64, 2);   // (diag block, m-half) -> 128 CTAs, one wave
    block_linear_wres<<<grid, THREADS, SMEM_TOTAL>>>(x, w, bias, y);
}

// round 17
// speedup vs baseline: 1.5292x; 1.3621x over previous
#include <cuda_runtime.h>
#include <cuda_fp16.h>
#include <cstdint>

// BlockLinear, weight-resident + warp-specialized.
// CTA = (nb, m-half): W[nb] -> fp16 smem once (132 KB resident).
// 8 compute warps (64x64 tiles over 128x256), 2 producer warps feeding a
// 4-stage A ring (K chunks of 64) via mbarrier full/empty pairs.

#define THREADS 320
#define NSTG 4
#define ARB 144                     // A row bytes: 9*16 -> conflict-free ldmatrix/STS
#define BRB 528                     // B row bytes: 33*16 -> conflict-free
#define A_STG (128 * ARB)           // 18432 B per stage
#define SM_A 0
#define SM_B (NSTG * A_STG)         // 73728
#define SM_BIAS (SM_B + 256 * BRB)  // 208896
#define SM_MBAR (SM_BIAS + 1024)    // empty[4] @ +0, full[4] @ +32
#define SMEM_TOTAL (SM_MBAR + 64)   // 209984 B

__device__ __forceinline__ uint32_t pk2(float a, float b) {
    __half2 h = __floats2half2_rn(a, b);
    return *reinterpret_cast<uint32_t*>(&h);
}
__device__ __forceinline__ void ldm4(uint32_t* r, uint32_t addr) {
    asm volatile("ldmatrix.sync.aligned.m8n8.x4.shared.b16 {%0,%1,%2,%3}, [%4];"
                 : "=r"(r[0]), "=r"(r[1]), "=r"(r[2]), "=r"(r[3]) : "r"(addr));
}
__device__ __forceinline__ void mma16816(float* c, const uint32_t* a, const uint32_t* b) {
    asm volatile(
        "mma.sync.aligned.m16n8k16.row.col.f32.f16.f16.f32 "
        "{%0,%1,%2,%3},{%4,%5,%6,%7},{%8,%9},{%0,%1,%2,%3};"
        : "+f"(c[0]), "+f"(c[1]), "+f"(c[2]), "+f"(c[3])
        : "r"(a[0]), "r"(a[1]), "r"(a[2]), "r"(a[3]), "r"(b[0]), "r"(b[1]));
}
__device__ __forceinline__ void mbar_init(uint32_t a, uint32_t cnt) {
    asm volatile("mbarrier.init.shared.b64 [%0], %1;" :: "r"(a), "r"(cnt) : "memory");
}
__device__ __forceinline__ void mbar_arrive(uint32_t a) {
    asm volatile("mbarrier.arrive.shared.b64 _, [%0];" :: "r"(a) : "memory");
}
__device__ __forceinline__ void mbar_wait(uint32_t a, uint32_t parity) {
    asm volatile(
        "{\n\t.reg .pred P1;\n\t"
        "WL_%=:\n\t"
        "mbarrier.try_wait.parity.acquire.cta.shared::cta.b64 P1, [%0], %1, 0x989680;\n\t"
        "@P1 bra.uni WD_%=;\n\t"
        "bra.uni WL_%=;\n\t"
        "WD_%=:\n\t}"
        :: "r"(a), "r"(parity) : "memory");
}

__global__ __launch_bounds__(THREADS, 1)
void block_linear_ws(const float* __restrict__ X, const float* __restrict__ W,
                     const float* __restrict__ Bias, float* __restrict__ Y)
{
    extern __shared__ unsigned char sm[];
    const uint32_t smu = (uint32_t)__cvta_generic_to_shared(sm);

    const int nb = blockIdx.x;          // diag block 0..63
    const int by = blockIdx.y;          // m-half 0..1 (16 slabs each)

    const int tid  = threadIdx.x;
    const int warp = tid >> 5;
    const int lane = tid & 31;

    // ---- setup: barriers, bias, resident W (threads 0-255) ----
    if (tid == 0) {
        #pragma unroll
        for (int s = 0; s < NSTG; ++s) {
            mbar_init(smu + SM_MBAR + s * 8, 256);       // empty[s]: consumers
            mbar_init(smu + SM_MBAR + 32 + s * 8, 64);   // full[s]:  producers
        }
    }
    if (tid < 256) {
        ((float*)(sm + SM_BIAS))[tid] = Bias[nb * 256 + tid];
        const float4* wr = (const float4*)(W + (size_t)nb * 65536 + (size_t)tid * 256);
        unsigned char* brow = sm + SM_B + tid * BRB;
        #pragma unroll 8
        for (int j = 0; j < 32; ++j) {
            float4 v0 = wr[2 * j], v1 = wr[2 * j + 1];
            uint4 o = {pk2(v0.x, v0.y), pk2(v0.z, v0.w), pk2(v1.x, v1.y), pk2(v1.z, v1.w)};
            *(uint4*)(brow + j * 16) = o;
        }
    }
    __syncthreads();

    if (warp >= 8) {
        // ================= PRODUCERS (warps 8-9, 64 threads) =================
        const int ptid = tid - 256;          // 0..63
        const int seg  = ptid & 15;          // 4-float k-segment within 64-col chunk
        const int rb   = ptid >> 4;          // row base 0..3 (rows rb + 4*i)
        const float* xb = X + (size_t)nb * 256 + seg * 4;

        #pragma unroll 1
        for (int c = 0; c < 64; ++c) {
            const int s = c & 3, t = c >> 2;
            const int m0 = (by * 16 + t) * 128;
            const int kb = s * 64;
            const float* xr = xb + kb;

            float4 r0[8], r1[8];
            #pragma unroll
            for (int j = 0; j < 8; ++j)
                r0[j] = *(const float4*)(xr + (size_t)(m0 + rb + 4 * j) * 16384);
            #pragma unroll
            for (int j = 0; j < 8; ++j)
                r1[j] = *(const float4*)(xr + (size_t)(m0 + rb + 4 * (8 + j)) * 16384);

            mbar_wait(smu + SM_MBAR + s * 8, 1u ^ (t & 1));   // empty[s]

            // packed fp16 row = 128 B; this thread's 4 floats -> 8 B at seg*8
            unsigned char* dst = sm + SM_A + s * A_STG + seg * 8;
            #pragma unroll
            for (int j = 0; j < 8; ++j) {
                float4 v = r0[j];
                *(uint2*)(dst + (rb + 4 * j) * ARB) =
                    make_uint2(pk2(v.x, v.y), pk2(v.z, v.w));
            }
            float4 r2[8], r3[8];
            #pragma unroll
            for (int j = 0; j < 8; ++j)
                r2[j] = *(const float4*)(xr + (size_t)(m0 + rb + 4 * (16 + j)) * 16384);
            #pragma unroll
            for (int j = 0; j < 8; ++j) {
                float4 v = r1[j];
                *(uint2*)(dst + (rb + 4 * (8 + j)) * ARB) =
                    make_uint2(pk2(v.x, v.y), pk2(v.z, v.w));
            }
            #pragma unroll
            for (int j = 0; j < 8; ++j)
                r3[j] = *(const float4*)(xr + (size_t)(m0 + rb + 4 * (24 + j)) * 16384);
            #pragma unroll
            for (int j = 0; j < 8; ++j) {
                float4 v = r2[j];
                *(uint2*)(dst + (rb + 4 * (16 + j)) * ARB) =
                    make_uint2(pk2(v.x, v.y), pk2(v.z, v.w));
            }
            #pragma unroll
            for (int j = 0; j < 8; ++j) {
                float4 v = r3[j];
                *(uint2*)(dst + (rb + 4 * (24 + j)) * ARB) =
                    make_uint2(pk2(v.x, v.y), pk2(v.z, v.w));
            }
            mbar_arrive(smu + SM_MBAR + 32 + s * 8);          // full[s]
        }
    } else {
        // ================= CONSUMERS (warps 0-7) =================
        const int wm = warp & 1;            // 2 warps along M (64 rows)
        const int wn = warp >> 1;           // 4 warps along N (64 cols)
        const int g  = lane >> 2;
        const int tg = lane & 3;

        const int la = lane & 15, ha = lane >> 4;
        const uint32_t aAddr = smu + SM_A + (wm * 64 + la) * ARB + ha * 16;
        const int lb = (lane & 7) + ((lane >> 4) << 3);
        const int cb = (lane >> 3) & 1;
        const uint32_t bAddr = smu + SM_B + (wn * 64 + lb) * BRB + cb * 16;

        float acc[4][8][4];
        #pragma unroll
        for (int mt = 0; mt < 4; ++mt)
            #pragma unroll
            for (int nt = 0; nt < 8; ++nt)
                #pragma unroll
                for (int i = 0; i < 4; ++i) acc[mt][nt][i] = 0.0f;

        #pragma unroll 1
        for (int c = 0; c < 64; ++c) {
            const int s = c & 3, t = c >> 2;

            mbar_wait(smu + SM_MBAR + 32 + s * 8, t & 1);     // full[s]

            const uint32_t aB = aAddr + s * A_STG;
            const uint32_t bB = bAddr + s * 128;
            #pragma unroll
            for (int ks = 0; ks < 4; ++ks) {
                uint32_t aF[4][4], bF[8][2];
                #pragma unroll
                for (int mt = 0; mt < 4; ++mt)
                    ldm4(aF[mt], aB + mt * 16 * ARB + ks * 32);
                #pragma unroll
                for (int q = 0; q < 4; ++q) {
                    uint32_t tr[4];
                    ldm4(tr, bB + q * 16 * BRB + ks * 32);
                    bF[2 * q][0]     = tr[0]; bF[2 * q][1]     = tr[1];
                    bF[2 * q + 1][0] = tr[2]; bF[2 * q + 1][1] = tr[3];
                }
                #pragma unroll
                for (int nt = 0; nt < 8; ++nt)
                    #pragma unroll
                    for (int mt = 0; mt < 4; ++mt)
                        mma16816(acc[mt][nt], aF[mt], bF[nt]);
            }
            mbar_arrive(smu + SM_MBAR + s * 8);               // empty[s]

            if (s == 3) {   // slab t done: epilogue overlaps next fills
                const int m0 = (by * 16 + t) * 128;
                const float* bs = (const float*)(sm + SM_BIAS);
                #pragma unroll
                for (int mt = 0; mt < 4; ++mt) {
                    const int row0 = m0 + wm * 64 + mt * 16 + g;
                    #pragma unroll
                    for (int nt = 0; nt < 8; ++nt) {
                        const int lcol = wn * 64 + nt * 8 + tg * 2;
                        const int gcol = nb * 256 + lcol;
                        const float b0 = bs[lcol], b1 = bs[lcol + 1];
                        float2 v0 = make_float2(acc[mt][nt][0] + b0, acc[mt][nt][1] + b1);
                        float2 v1 = make_float2(acc[mt][nt][2] + b0, acc[mt][nt][3] + b1);
                        *(float2*)(Y + (size_t)row0       * 16384 + gcol) = v0;
                        *(float2*)(Y + (size_t)(row0 + 8) * 16384 + gcol) = v1;
                        acc[mt][nt][0] = 0.0f; acc[mt][nt][1] = 0.0f;
                        acc[mt][nt][2] = 0.0f; acc[mt][nt][3] = 0.0f;
                    }
                }
            }
        }
    }
}

extern "C" void kernel_launch(void* const* d_in, const int* in_sizes, int n_in,
                              void* d_out, int out_size) {
    const float* x    = (const float*)d_in[0];
    const float* w    = (const float*)d_in[1];
    const float* bias = (const float*)d_in[2];
    float* y          = (float*)d_out;

    cudaFuncSetAttribute(block_linear_ws,
                         cudaFuncAttributeMaxDynamicSharedMemorySize, SMEM_TOTAL);
    dim3 grid(64, 2);   // (diag block, m-half) -> 128 CTAs, one wave
    block_linear_ws<<<grid, THREADS, SMEM_TOTAL>>>(x, w, bias, y);
}